// round 4
// baseline (speedup 1.0000x reference)
#include <cuda_runtime.h>
#include <math.h>

#define SW 21
#define PAD 10
#define IMH 256
#define IMW 256
#define PW 276            // 256 + 2*PAD
#define HW (IMH*IMW)
#define RSTRIP 8
#define NSTRIP (IMH / RSTRIP)   // 32
#define NGROUP 21
#define NT 288            // 9 warps; threads 0..275 handle padded cols, 0..255 handle outputs

// -------- scratch (no cudaMalloc allowed) --------
__device__ float g_ypad[PW * PW];          // reflect-padded luminance of clipped rgb
__device__ float g_rgbpad[3][PW * PW];     // reflect-padded raw rgb
__device__ float g_acc[NGROUP][4][HW];     // per-dy-group partial (numR,numG,numB,den)

// reflect index for np.pad(mode='reflect'): -1 -> 1, 256 -> 254. valid for i in [-255, 510]
__device__ __forceinline__ int refl(int i) {
    i = (i < 0) ? -i : i;
    return (i > 255) ? (510 - i) : i;
}

// -------- kernel 1: build padded luminance + padded rgb --------
__global__ void prep_kernel(const float* __restrict__ rgb) {
    int idx = blockIdx.x * blockDim.x + threadIdx.x;
    if (idx >= PW * PW) return;
    int I = idx / PW;
    int J = idx - I * PW;
    int p = refl(I - PAD) * IMW + refl(J - PAD);
    float r = rgb[p];
    float g = rgb[HW + p];
    float b = rgb[2 * HW + p];
    g_rgbpad[0][idx] = r;
    g_rgbpad[1][idx] = g;
    g_rgbpad[2][idx] = b;
    float rc = fminf(fmaxf(r, 0.f), 1.f);
    float gc = fminf(fmaxf(g, 0.f), 1.f);
    float bc = fminf(fmaxf(b, 0.f), 1.f);
    g_ypad[idx] = 0.299f * rc + 0.587f * gc + 0.114f * bc;
}

// -------- kernel 2: main NLM. grid = (NSTRIP, NGROUP), block = NT --------
// CTA (s, g): rows [s*RSTRIP, s*RSTRIP+RSTRIP), offset row dy = g-10, loops dx = -10..10.
// Thread t: padded column j = t-10 (t < 276) for the sliding vertical sum; output column w = t (t < 256).
__global__ __launch_bounds__(NT, 2)
void nlm_kernel(const float* __restrict__ hparam) {
    __shared__ float s_cs[2][PW];   // double-buffered column sums (V), indexed by j+PAD = t

    const int t  = threadIdx.x;
    const int h0 = blockIdx.x * RSTRIP;
    const int dy = (int)blockIdx.y - PAD;

    const float hr    = fmaxf(hparam[0], 0.f) + 1e-8f;
    const float inv_h = 1.0f / hr;
    const float dmax  = (34.0f * hr) * (34.0f * hr);   // weight <= e^-34 below threshold -> skip

    const bool colA = (t < PW);
    const int  ji   = colA ? refl(t - PAD) : 0;        // inactive threads use safe col 0
    const bool outA = (t < IMW);

    float accR[RSTRIP], accG[RSTRIP], accB[RSTRIP], accD[RSTRIP];
#pragma unroll
    for (int i = 0; i < RSTRIP; i++) { accR[i] = 0.f; accG[i] = 0.f; accB[i] = 0.f; accD[i] = 0.f; }

    for (int dxi = 0; dxi < SW; dxi++) {
        const int dx = dxi - PAD;
        const int cA = ji + PAD;         // center column in ypad
        const int cB = ji + dx + PAD;    // shifted column in ypad

        // ---- prime vertical window: rows h0-10 .. h0+10, kept in a register ring ----
        float pr[SW];
        float csum = 0.f;
#pragma unroll
        for (int rr = 0; rr < SW; rr++) {
            int ri = refl(h0 - PAD + rr);
            float a = g_ypad[(ri + PAD) * PW + cA];
            float b = g_ypad[(ri + dy + PAD) * PW + cB];
            float df = a - b;
            float d = df * df;
            pr[rr] = d;
            csum += d;
        }

        // ---- slide over output rows ----
#pragma unroll
        for (int row = 0; row < RSTRIP; row++) {
            if (row > 0) {
                int ri = refl(h0 + PAD + row);
                float a = g_ypad[(ri + PAD) * PW + cA];
                float b = g_ypad[(ri + dy + PAD) * PW + cB];
                float df = a - b;
                csum += df * df - pr[row - 1];   // RSTRIP<=21: ring never wraps
            }
            if (colA) s_cs[row & 1][t] = csum;
            __syncthreads();   // single barrier per row; buffer parity protects the other direction

            if (outA) {
                float v[SW];
#pragma unroll
                for (int i = 0; i < SW; i++) v[i] = s_cs[row & 1][t + i];
                // balanced tree sum
                float s1 = (v[0] + v[1]) + (v[2] + v[3]);
                float s2 = (v[4] + v[5]) + (v[6] + v[7]);
                float s3 = (v[8] + v[9]) + (v[10] + v[11]);
                float s4 = (v[12] + v[13]) + (v[14] + v[15]);
                float s5 = (v[16] + v[17]) + (v[18] + v[19]);
                float D  = ((s1 + s2) + (s3 + s4)) + (s5 + v[20]);

                if (D < dmax) {
                    D = fmaxf(D, 0.f);
                    float wgt = expf(-sqrtf(D) * inv_h);
                    int rp = (h0 + row + dy + PAD) * PW + (t + dx + PAD);
                    accR[row] += wgt * g_rgbpad[0][rp];
                    accG[row] += wgt * g_rgbpad[1][rp];
                    accB[row] += wgt * g_rgbpad[2][rp];
                    accD[row] += wgt;
                }
            }
        }
    }

    // ---- exclusive write of this (strip, group) slice ----
    if (outA) {
        const int g = blockIdx.y;
#pragma unroll
        for (int row = 0; row < RSTRIP; row++) {
            int p = (h0 + row) * IMW + t;
            g_acc[g][0][p] = accR[row];
            g_acc[g][1][p] = accG[row];
            g_acc[g][2][p] = accB[row];
            g_acc[g][3][p] = accD[row];
        }
    }
}

// -------- kernel 3: reduce the 21 dy-group partials, normalize, clip --------
__global__ void reduce_kernel(float* __restrict__ out) {
    int p = blockIdx.x * blockDim.x + threadIdx.x;
    if (p >= HW) return;
    float nr = 0.f, ng = 0.f, nb = 0.f, dn = 0.f;
#pragma unroll
    for (int g = 0; g < NGROUP; g++) {
        nr += g_acc[g][0][p];
        ng += g_acc[g][1][p];
        nb += g_acc[g][2][p];
        dn += g_acc[g][3][p];
    }
    float id = 1.0f / dn;   // dn >= 1 always (center offset weight == 1)
    out[p]          = fminf(fmaxf(nr * id, 0.f), 1.f);
    out[HW + p]     = fminf(fmaxf(ng * id, 0.f), 1.f);
    out[2 * HW + p] = fminf(fmaxf(nb * id, 0.f), 1.f);
}

extern "C" void kernel_launch(void* const* d_in, const int* in_sizes, int n_in,
                              void* d_out, int out_size) {
    const float* rgb = (const float*)d_in[0];
    const float* hp  = (const float*)d_in[1];
    // defensive: metadata order is (rgb[196608], h[1]); swap if sizes say otherwise
    if (n_in >= 2 && in_sizes[0] == 1) {
        rgb = (const float*)d_in[1];
        hp  = (const float*)d_in[0];
    }
    prep_kernel<<<(PW * PW + 255) / 256, 256>>>(rgb);
    nlm_kernel<<<dim3(NSTRIP, NGROUP), NT>>>(hp);
    reduce_kernel<<<(HW + 255) / 256, 256>>>((float*)d_out);
}

// round 5
// speedup vs baseline: 3.4895x; 3.4895x over previous
#include <cuda_runtime.h>
#include <math.h>

#define SW 21
#define PAD 10
#define IMH 256
#define IMW 256
#define PW 276            // 256 + 2*PAD
#define HW (IMH*IMW)
#define RSTRIP 8
#define NSTRIP (IMH / RSTRIP)   // 32
#define NGROUP 21
#define NT 288            // 9 warps
#define NROWS 28          // RSTRIP + 2*PAD window rows per strip

// -------- scratch (no cudaMalloc allowed) --------
__device__ float g_ypad[PW * PW];          // reflect-padded luminance of clipped rgb
__device__ float g_rgbpad[3][PW * PW];     // reflect-padded raw rgb
__device__ float g_acc[NGROUP][4][HW];     // per-dy-group partial (numR,numG,numB,den)

// reflect index for np.pad(mode='reflect'): -1 -> 1, 256 -> 254
__device__ __forceinline__ int refl(int i) {
    i = (i < 0) ? -i : i;
    return (i > 255) ? (510 - i) : i;
}

// -------- kernel 1: build padded luminance + padded rgb --------
__global__ void prep_kernel(const float* __restrict__ rgb) {
    int idx = blockIdx.x * blockDim.x + threadIdx.x;
    if (idx >= PW * PW) return;
    int I = idx / PW;
    int J = idx - I * PW;
    int p = refl(I - PAD) * IMW + refl(J - PAD);
    float r = rgb[p];
    float g = rgb[HW + p];
    float b = rgb[2 * HW + p];
    g_rgbpad[0][idx] = r;
    g_rgbpad[1][idx] = g;
    g_rgbpad[2][idx] = b;
    float rc = fminf(fmaxf(r, 0.f), 1.f);
    float gc = fminf(fmaxf(g, 0.f), 1.f);
    float bc = fminf(fmaxf(b, 0.f), 1.f);
    g_ypad[idx] = 0.299f * rc + 0.587f * gc + 0.114f * bc;
}

// -------- kernel 2: main NLM. grid = (NSTRIP, NGROUP), block = NT --------
// CTA (s, g): output rows [s*8, s*8+8), dy = g-10, loops dx = -10..10.
// Phase A (t<276): build column sums CS[8][276] via vertical sliding window (SMEM-staged rows).
// Phase B (t<256): ty=t>>5 row, tx=t&31 -> 8-col segment; horizontal sliding 21-sum from CS.
__global__ void __launch_bounds__(NT, 2) nlm_kernel(const float* __restrict__ hparam) {
    extern __shared__ float sm[];
    float* s_yA = sm;                    // [NROWS][PW] center rows (pre-reflected)
    float* s_yB = sm + NROWS * PW;       // [NROWS][PW] rows shifted by dy
    float* s_cs = sm + 2 * NROWS * PW;   // [RSTRIP][PW] per-row vertical column sums

    const int t  = threadIdx.x;
    const int h0 = blockIdx.x * RSTRIP;
    const int dy = (int)blockIdx.y - PAD;

    const float hr    = fmaxf(hparam[0], 0.f) + 1e-8f;
    const float inv_h = 1.0f / hr;
    const float dmax  = (34.0f * hr) * (34.0f * hr);   // weight <= e^-34 below -> skip

    // ---- stage the two row streams (reflect resolved here, once) ----
    if (t < PW) {
#pragma unroll
        for (int rr = 0; rr < NROWS; rr++) {
            int rA = refl(h0 - PAD + rr) + PAD;     // ypad row index, in [10,265]
            s_yA[rr * PW + t] = g_ypad[rA * PW + t];
            s_yB[rr * PW + t] = g_ypad[(rA + dy) * PW + t];  // rA+dy in [0,275]
        }
    }
    __syncthreads();

    const bool colA = (t < PW);
    const int  cA   = colA ? (refl(t - PAD) + PAD) : PAD;   // column-reflect, hoisted
    const bool outA = (t < IMW);
    const int  ty   = t >> 5;          // row within strip (0..7) for phase B
    const int  tx   = t & 31;          // 8-col segment id
    const int  w0   = tx * 8;

    float accR[8], accG[8], accB[8], accD[8];
#pragma unroll
    for (int i = 0; i < 8; i++) { accR[i] = 0.f; accG[i] = 0.f; accB[i] = 0.f; accD[i] = 0.f; }

    const int orow  = h0 + ty;                       // output row (phase B)
    const int rbase = (orow + dy + PAD) * PW;        // + (col+dx+PAD) later

    for (int dxi = 0; dxi < SW; dxi++) {
        const int dx = dxi - PAD;

        // ---- phase A: vertical sliding column sums ----
        if (colA) {
            const float* pA = s_yA + cA;
            const float* pB = s_yB + cA + dx;        // cA+dx in [0,275]
            float pr[7];
            float csum = 0.f;
#pragma unroll
            for (int rr = 0; rr < 21; rr++) {
                float d = pA[rr * PW] - pB[rr * PW];
                if (rr < 7) pr[rr] = d;
                csum = fmaf(d, d, csum);
            }
            s_cs[t] = csum;
#pragma unroll
            for (int k = 1; k < 8; k++) {
                float d = pA[(20 + k) * PW] - pB[(20 + k) * PW];
                csum = fmaf(d, d, csum);
                float o = pr[k - 1];
                csum = fmaf(-o, o, csum);
                s_cs[k * PW + t] = csum;
            }
        }
        __syncthreads();

        // ---- phase B: horizontal sliding 21-sum over 8 outputs ----
        if (outA) {
            const float4* row4 = (const float4*)(s_cs + ty * PW) + tx * 2;  // 16B aligned
            float a[28];
#pragma unroll
            for (int q = 0; q < 7; q++) {
                float4 v = row4[q];
                a[4 * q + 0] = v.x; a[4 * q + 1] = v.y;
                a[4 * q + 2] = v.z; a[4 * q + 3] = v.w;
            }
            // D for first output (tree sum of a[0..20])
            float s1 = (a[0] + a[1]) + (a[2] + a[3]);
            float s2 = (a[4] + a[5]) + (a[6] + a[7]);
            float s3 = (a[8] + a[9]) + (a[10] + a[11]);
            float s4 = (a[12] + a[13]) + (a[14] + a[15]);
            float s5 = (a[16] + a[17]) + (a[18] + a[19]);
            float D  = ((s1 + s2) + (s3 + s4)) + (s5 + a[20]);

#pragma unroll
            for (int k = 0; k < 8; k++) {
                if (D < dmax) {
                    float Dc  = fmaxf(D, 0.f);
                    float wgt = expf(-sqrtf(Dc) * inv_h);
                    int rp = rbase + (w0 + k + dx + PAD);
                    accR[k] = fmaf(wgt, g_rgbpad[0][rp], accR[k]);
                    accG[k] = fmaf(wgt, g_rgbpad[1][rp], accG[k]);
                    accB[k] = fmaf(wgt, g_rgbpad[2][rp], accB[k]);
                    accD[k] += wgt;
                }
                if (k < 7) D += a[k + 21] - a[k];
            }
        }
        __syncthreads();   // protect s_cs before next dx overwrites it
    }

    // ---- exclusive coalesced writeout of this (strip, group) slice ----
    if (outA) {
        const int g = blockIdx.y;
        int p = orow * IMW + w0;
        *(float4*)&g_acc[g][0][p]     = make_float4(accR[0], accR[1], accR[2], accR[3]);
        *(float4*)&g_acc[g][0][p + 4] = make_float4(accR[4], accR[5], accR[6], accR[7]);
        *(float4*)&g_acc[g][1][p]     = make_float4(accG[0], accG[1], accG[2], accG[3]);
        *(float4*)&g_acc[g][1][p + 4] = make_float4(accG[4], accG[5], accG[6], accG[7]);
        *(float4*)&g_acc[g][2][p]     = make_float4(accB[0], accB[1], accB[2], accB[3]);
        *(float4*)&g_acc[g][2][p + 4] = make_float4(accB[4], accB[5], accB[6], accB[7]);
        *(float4*)&g_acc[g][3][p]     = make_float4(accD[0], accD[1], accD[2], accD[3]);
        *(float4*)&g_acc[g][3][p + 4] = make_float4(accD[4], accD[5], accD[6], accD[7]);
    }
}

// -------- kernel 3: reduce the 21 dy-group partials, normalize, clip --------
__global__ void reduce_kernel(float* __restrict__ out) {
    int p = blockIdx.x * blockDim.x + threadIdx.x;
    if (p >= HW) return;
    float nr = 0.f, ng = 0.f, nb = 0.f, dn = 0.f;
#pragma unroll
    for (int g = 0; g < NGROUP; g++) {
        nr += g_acc[g][0][p];
        ng += g_acc[g][1][p];
        nb += g_acc[g][2][p];
        dn += g_acc[g][3][p];
    }
    float id = 1.0f / dn;   // dn >= 1 always (center offset weight == 1)
    out[p]          = fminf(fmaxf(nr * id, 0.f), 1.f);
    out[HW + p]     = fminf(fmaxf(ng * id, 0.f), 1.f);
    out[2 * HW + p] = fminf(fmaxf(nb * id, 0.f), 1.f);
}

extern "C" void kernel_launch(void* const* d_in, const int* in_sizes, int n_in,
                              void* d_out, int out_size) {
    const float* rgb = (const float*)d_in[0];
    const float* hp  = (const float*)d_in[1];
    if (n_in >= 2 && in_sizes[0] == 1) {   // defensive input-order check
        rgb = (const float*)d_in[1];
        hp  = (const float*)d_in[0];
    }
    const int smem_bytes = (2 * NROWS + RSTRIP) * PW * sizeof(float);  // 70,656 B
    static bool attr_set = false;
    if (!attr_set) {
        cudaFuncSetAttribute(nlm_kernel, cudaFuncAttributeMaxDynamicSharedMemorySize, smem_bytes);
        attr_set = true;
    }
    prep_kernel<<<(PW * PW + 255) / 256, 256>>>(rgb);
    nlm_kernel<<<dim3(NSTRIP, NGROUP), NT, smem_bytes>>>(hp);
    reduce_kernel<<<(HW + 255) / 256, 256>>>((float*)d_out);
}

// round 8
// speedup vs baseline: 3.6629x; 1.0497x over previous
#include <cuda_runtime.h>
#include <math.h>

#define SW 21
#define PAD 10
#define IMH 256
#define IMW 256
#define PW 276            // 256 + 2*PAD
#define HW (IMH*IMW)
#define RSTRIP 8
#define NSTRIP (IMH / RSTRIP)   // 32
#define NGROUP 21
#define NT 288            // 9 warps
#define NROWS 28          // RSTRIP + 2*PAD window rows per strip

// -------- scratch (no cudaMalloc allowed) --------
__device__ float g_ypad[PW * PW];          // reflect-padded luminance of clipped rgb
__device__ float g_rgbpad[3][PW * PW];     // reflect-padded raw rgb
__device__ float g_acc[NGROUP][4][HW];     // per-dy-group partial (numR,numG,numB,den)

// reflect index for np.pad(mode='reflect'): -1 -> 1, 256 -> 254
__device__ __forceinline__ int refl(int i) {
    i = (i < 0) ? -i : i;
    return (i > 255) ? (510 - i) : i;
}

// -------- kernel 1: build padded luminance + padded rgb --------
__global__ void prep_kernel(const float* __restrict__ rgb) {
    int idx = blockIdx.x * blockDim.x + threadIdx.x;
    if (idx >= PW * PW) return;
    int I = idx / PW;
    int J = idx - I * PW;
    int p = refl(I - PAD) * IMW + refl(J - PAD);
    float r = rgb[p];
    float g = rgb[HW + p];
    float b = rgb[2 * HW + p];
    g_rgbpad[0][idx] = r;
    g_rgbpad[1][idx] = g;
    g_rgbpad[2][idx] = b;
    float rc = fminf(fmaxf(r, 0.f), 1.f);
    float gc = fminf(fmaxf(g, 0.f), 1.f);
    float bc = fminf(fmaxf(b, 0.f), 1.f);
    g_ypad[idx] = 0.299f * rc + 0.587f * gc + 0.114f * bc;
}

// -------- kernel 2: main NLM. grid = (NSTRIP, NGROUP), block = NT --------
// CTA (s, g): output rows [s*8, s*8+8), dy = g-10, loops dx = -10..10.
// A-stream (center column, dx-invariant) lives in REGISTERS (yA[28]).
// B-stream (dy-shifted rows) staged once in SMEM; column sums CS double-buffered
// so each dx iteration needs exactly ONE barrier.
__global__ void __launch_bounds__(NT, 2) nlm_kernel(const float* __restrict__ hparam) {
    __shared__ float s_yB[NROWS * PW];        // rows shifted by dy (pre-reflected)
    __shared__ float s_cs[2][RSTRIP * PW];    // double-buffered per-row vertical column sums

    const int t  = threadIdx.x;
    const int h0 = blockIdx.x * RSTRIP;
    const int dy = (int)blockIdx.y - PAD;

    const float hr    = fmaxf(hparam[0], 0.f) + 1e-8f;
    const float inv_h = 1.0f / hr;
    const float dmax  = (34.0f * hr) * (34.0f * hr);   // weight <= e^-34 below -> skip

    const bool colA = (t < PW);
    const int  cA   = colA ? (refl(t - PAD) + PAD) : PAD;   // column reflect, hoisted
    const bool outA = (t < IMW);
    const int  ty   = t >> 5;          // row within strip (0..7) for phase B
    const int  tx   = t & 31;          // 8-col segment id
    const int  w0   = tx * 8;

    // ---- stage B rows to SMEM; hoist A column to registers ----
    float yA[NROWS];
    if (colA) {
#pragma unroll
        for (int rr = 0; rr < NROWS; rr++) {
            int rA = refl(h0 - PAD + rr) + PAD;              // ypad row, in [10,265]
            s_yB[rr * PW + t] = g_ypad[(rA + dy) * PW + t];  // rA+dy in [0,275]
            yA[rr] = g_ypad[rA * PW + cA];
        }
    }
    __syncthreads();

    float accR[8], accG[8], accB[8], accD[8];
#pragma unroll
    for (int i = 0; i < 8; i++) { accR[i] = 0.f; accG[i] = 0.f; accB[i] = 0.f; accD[i] = 0.f; }

    const int orow  = h0 + ty;                       // output row (phase B)
    const int rbase = (orow + dy + PAD) * PW;        // + (col+dx+PAD) later

    for (int dxi = 0; dxi < SW; dxi++) {
        const int dx = dxi - PAD;
        float* cs = s_cs[dxi & 1];

        // ---- phase A: vertical sliding column sums (A in regs, B from SMEM) ----
        if (colA) {
            const float* pB = s_yB + cA + dx;        // cA+dx in [0,275]
            float pr[7];
            float csum = 0.f;
#pragma unroll
            for (int rr = 0; rr < 21; rr++) {
                float d = yA[rr] - pB[rr * PW];
                if (rr < 7) pr[rr] = d;
                csum = fmaf(d, d, csum);
            }
            cs[t] = csum;
#pragma unroll
            for (int k = 1; k < 8; k++) {
                float d = yA[20 + k] - pB[(20 + k) * PW];
                csum = fmaf(d, d, csum);
                float o = pr[k - 1];
                csum = fmaf(-o, o, csum);
                cs[k * PW + t] = csum;
            }
        }
        __syncthreads();   // single barrier: orders A(i) writes before B(i) reads,
                           // and B(i-1) reads before A(i+1) writes (other buffer parity)

        // ---- phase B: horizontal sliding 21-sum over 8 outputs ----
        if (outA) {
            const float4* row4 = (const float4*)(cs + ty * PW) + tx * 2;  // 16B aligned
            float a[28];
#pragma unroll
            for (int q = 0; q < 7; q++) {
                float4 v = row4[q];
                a[4 * q + 0] = v.x; a[4 * q + 1] = v.y;
                a[4 * q + 2] = v.z; a[4 * q + 3] = v.w;
            }
            float s1 = (a[0] + a[1]) + (a[2] + a[3]);
            float s2 = (a[4] + a[5]) + (a[6] + a[7]);
            float s3 = (a[8] + a[9]) + (a[10] + a[11]);
            float s4 = (a[12] + a[13]) + (a[14] + a[15]);
            float s5 = (a[16] + a[17]) + (a[18] + a[19]);
            float D  = ((s1 + s2) + (s3 + s4)) + (s5 + a[20]);

#pragma unroll
            for (int k = 0; k < 8; k++) {
                if (D < dmax) {
                    float Dc  = fmaxf(D, 0.f);
                    float wgt = expf(-sqrtf(Dc) * inv_h);
                    int rp = rbase + (w0 + k + dx + PAD);
                    accR[k] = fmaf(wgt, g_rgbpad[0][rp], accR[k]);
                    accG[k] = fmaf(wgt, g_rgbpad[1][rp], accG[k]);
                    accB[k] = fmaf(wgt, g_rgbpad[2][rp], accB[k]);
                    accD[k] += wgt;
                }
                if (k < 7) D += a[k + 21] - a[k];
            }
        }
        // no trailing barrier: next iteration writes the other cs buffer
    }

    // ---- exclusive coalesced writeout of this (strip, group) slice ----
    if (outA) {
        const int g = blockIdx.y;
        int p = orow * IMW + w0;
        *(float4*)&g_acc[g][0][p]     = make_float4(accR[0], accR[1], accR[2], accR[3]);
        *(float4*)&g_acc[g][0][p + 4] = make_float4(accR[4], accR[5], accR[6], accR[7]);
        *(float4*)&g_acc[g][1][p]     = make_float4(accG[0], accG[1], accG[2], accG[3]);
        *(float4*)&g_acc[g][1][p + 4] = make_float4(accG[4], accG[5], accG[6], accG[7]);
        *(float4*)&g_acc[g][2][p]     = make_float4(accB[0], accB[1], accB[2], accB[3]);
        *(float4*)&g_acc[g][2][p + 4] = make_float4(accB[4], accB[5], accB[6], accB[7]);
        *(float4*)&g_acc[g][3][p]     = make_float4(accD[0], accD[1], accD[2], accD[3]);
        *(float4*)&g_acc[g][3][p + 4] = make_float4(accD[4], accD[5], accD[6], accD[7]);
    }
}

// -------- kernel 3: reduce the 21 dy-group partials, normalize, clip (4 px/thread) --------
__global__ void reduce_kernel(float* __restrict__ out) {
    int q = blockIdx.x * blockDim.x + threadIdx.x;   // float4 index
    if (q >= HW / 4) return;
    float4 nr = make_float4(0.f, 0.f, 0.f, 0.f);
    float4 ng = nr, nb = nr, dn = nr;
#pragma unroll
    for (int g = 0; g < NGROUP; g++) {
        float4 v;
        v = ((const float4*)g_acc[g][0])[q]; nr.x += v.x; nr.y += v.y; nr.z += v.z; nr.w += v.w;
        v = ((const float4*)g_acc[g][1])[q]; ng.x += v.x; ng.y += v.y; ng.z += v.z; ng.w += v.w;
        v = ((const float4*)g_acc[g][2])[q]; nb.x += v.x; nb.y += v.y; nb.z += v.z; nb.w += v.w;
        v = ((const float4*)g_acc[g][3])[q]; dn.x += v.x; dn.y += v.y; dn.z += v.z; dn.w += v.w;
    }
    float4 o0, o1, o2;
    o0.x = fminf(fmaxf(nr.x / dn.x, 0.f), 1.f);
    o0.y = fminf(fmaxf(nr.y / dn.y, 0.f), 1.f);
    o0.z = fminf(fmaxf(nr.z / dn.z, 0.f), 1.f);
    o0.w = fminf(fmaxf(nr.w / dn.w, 0.f), 1.f);
    o1.x = fminf(fmaxf(ng.x / dn.x, 0.f), 1.f);
    o1.y = fminf(fmaxf(ng.y / dn.y, 0.f), 1.f);
    o1.z = fminf(fmaxf(ng.z / dn.z, 0.f), 1.f);
    o1.w = fminf(fmaxf(ng.w / dn.w, 0.f), 1.f);
    o2.x = fminf(fmaxf(nb.x / dn.x, 0.f), 1.f);
    o2.y = fminf(fmaxf(nb.y / dn.y, 0.f), 1.f);
    o2.z = fminf(fmaxf(nb.z / dn.z, 0.f), 1.f);
    o2.w = fminf(fmaxf(nb.w / dn.w, 0.f), 1.f);
    ((float4*)out)[q]              = o0;
    ((float4*)(out + HW))[q]       = o1;
    ((float4*)(out + 2 * HW))[q]   = o2;
}

extern "C" void kernel_launch(void* const* d_in, const int* in_sizes, int n_in,
                              void* d_out, int out_size) {
    const float* rgb = (const float*)d_in[0];
    const float* hp  = (const float*)d_in[1];
    if (n_in >= 2 && in_sizes[0] == 1) {   // defensive input-order check
        rgb = (const float*)d_in[1];
        hp  = (const float*)d_in[0];
    }
    prep_kernel<<<(PW * PW + 255) / 256, 256>>>(rgb);
    nlm_kernel<<<dim3(NSTRIP, NGROUP), NT>>>(hp);
    reduce_kernel<<<(HW / 4 + 255) / 256, 256>>>((float*)d_out);
}